// round 14
// baseline (speedup 1.0000x reference)
#include <cuda_runtime.h>
#include <cuda_bf16.h>
#include <cuda_fp16.h>
#include <cstdint>

#define TV 6400           // T*V = 256*25
#define NBATCH 64

// ---------------- scratch (device globals; no allocation allowed) ----------
__device__ __nv_bfloat16 g_zy[52428800];   // (64,128,6400) bf16: y pre-BN
__device__ __half g_zdh[52428800];         // (64,128,6400) fp16: down pre-BN
__device__ float g_part[3840000];   // (64,3,32,625) logits partials, [w*25+v]
__device__ float g_S[120000];       // (64,3,25,25) S^T: [w][v]
__device__ float g_Atot[1875];      // A + PA  ([v][w])
__device__ float g_by[128];         // sum_i bd[i]
__device__ float g_bab_pad[256];    // [ba|bb|0pad]
__device__ float g_alpha[256];      // BN fused scale
__device__ float g_bet[256];        // BN fused shift
__device__ float g_psum[1048576];   // (2,64,64,128) per-block channel sums
__device__ float g_psq[1048576];    // (2,64,64,128) per-block channel sumsq
// weights pre-packed in m16n8k16 A-fragment order (hi uint4 then lo uint4 per lane)
__device__ __align__(16) unsigned g_Wabf[16384];  // 16 mb x 4 ks x 32 x 8
__device__ __align__(16) unsigned g_Wyf[24576];   // 8 mb x 12 ks x 32 x 8
__device__ __align__(16) unsigned g_Wdnf[8192];   // 8 mb x 4 ks x 32 x 8

// ---------------- bf16 hi/lo split helpers ---------------------------------
__device__ __forceinline__ unsigned short bf_hi(float v) {
    return __bfloat16_as_ushort(__float2bfloat16(v));
}
__device__ __forceinline__ unsigned short bf_lo(float v) {
    __nv_bfloat16 h = __float2bfloat16(v);
    return __bfloat16_as_ushort(__float2bfloat16(v - __bfloat162float(h)));
}
__device__ __forceinline__ unsigned pack_hi(float v0, float v1) {
    return (unsigned)bf_hi(v0) | ((unsigned)bf_hi(v1) << 16);
}
__device__ __forceinline__ unsigned pack_lo(float v0, float v1) {
    return (unsigned)bf_lo(v0) | ((unsigned)bf_lo(v1) << 16);
}

// ---------------- prep: biases, A+PA, fragment-packed weights --------------
__device__ __forceinline__ void frag_decode(int f, int nK16,
                                            int& row, int& col, bool& hi) {
    int r = f & 7, slot = f >> 3;
    int lane = slot & 31, t2 = slot >> 5;
    int ks = t2 % nK16, mb = t2 / nK16;
    int rr = r & 3;
    row = mb * 16 + (lane >> 2) + ((rr & 1) << 3);
    col = ks * 16 + (lane & 3) * 2 + ((rr & 2) << 2);
    hi = r < 4;
}

__global__ __launch_bounds__(256) void prep_kernel(
    const float* __restrict__ Wa, const float* __restrict__ ba,
    const float* __restrict__ Wb, const float* __restrict__ bb,
    const float* __restrict__ Wd, const float* __restrict__ bd,
    const float* __restrict__ Wdown,
    const float* __restrict__ A,  const float* __restrict__ PA)
{
    int stride = gridDim.x * blockDim.x;
    int g = blockIdx.x * blockDim.x + threadIdx.x;
    for (int f = g; f < 256; f += stride)
        g_bab_pad[f] = (f < 96) ? ba[f] : (f < 192 ? bb[f - 96] : 0.f);
    for (int f = g; f < 128; f += stride)
        g_by[f] = bd[f] + bd[128 + f] + bd[256 + f];
    for (int f = g; f < 1875; f += stride)
        g_Atot[f] = A[f] + PA[f];

    for (int f = g; f < 16384; f += stride) {
        int row, col; bool hi;
        frag_decode(f, 4, row, col, hi);
        float v0 = 0.f, v1 = 0.f;
        if (row < 96)       { v0 = Wa[row * 64 + col]; v1 = Wa[row * 64 + col + 1]; }
        else if (row < 192) { v0 = Wb[(row - 96) * 64 + col]; v1 = Wb[(row - 96) * 64 + col + 1]; }
        g_Wabf[f] = hi ? pack_hi(v0, v1) : pack_lo(v0, v1);
    }
    for (int f = g; f < 24576; f += stride) {
        int row, col; bool hi;
        frag_decode(f, 12, row, col, hi);
        int i = col >> 6, c = col & 63;
        float v0 = Wd[(i * 128 + row) * 64 + c];
        float v1 = Wd[(i * 128 + row) * 64 + c + 1];
        g_Wyf[f] = hi ? pack_hi(v0, v1) : pack_lo(v0, v1);
    }
    for (int f = g; f < 8192; f += stride) {
        int row, col; bool hi;
        frag_decode(f, 4, row, col, hi);
        float v0 = Wdown[row * 64 + col], v1 = Wdown[row * 64 + col + 1];
        g_Wdnf[f] = hi ? pack_hi(v0, v1) : pack_lo(v0, v1);
    }
}

// ---------------- mma.sync wrapper -----------------------------------------
__device__ __forceinline__ void mma16816(float* c, const uint4& a,
                                         unsigned b0, unsigned b1) {
    asm volatile(
        "mma.sync.aligned.m16n8k16.row.col.f32.bf16.bf16.f32 "
        "{%0,%1,%2,%3}, {%4,%5,%6,%7}, {%8,%9}, {%0,%1,%2,%3};"
        : "+f"(c[0]), "+f"(c[1]), "+f"(c[2]), "+f"(c[3])
        : "r"(a.x), "r"(a.y), "r"(a.z), "r"(a.w), "r"(b0), "r"(b1));
}

// ========== fused a/b conv + logits partials; no a/b gmem round-trip =======
// grid (32 pt, 64 n); P-tile = 200 positions (8 whole t's). Block 256.
#define XP 66    // Xh pitch (odd word stride -> conflict-free)
#define AP 136   // At/Bt pitch

__global__ __launch_bounds__(256, 2) void ablogits_k(const float* __restrict__ x) {
    __shared__ __align__(16) unsigned short Xh[200][XP];
    __shared__ __align__(16) unsigned short At[32][AP];  // a^T: [v][r*8+tl]
    __shared__ __align__(16) unsigned short Bt[32][AP];  // b^T: [w][r*8+tl]
    int tid = threadIdx.x, wid = tid >> 5, lane = tid & 31;
    int pt = blockIdx.x, n = blockIdx.y;
    int lr = lane >> 2, lc2 = (lane & 3) * 2;
    int pBase = pt * 200;

    // stage X tile: 64 ch x 200 pos, bf16-hi, pos-major
    const float* xb = x + (long)n * (64L * TV) + pBase;
    for (int f = tid; f < 12800; f += 256) {
        int c = f / 200, p = f - c * 200;
        Xh[p][c] = bf_hi(xb[(long)c * TV + p]);
    }

    int ab = wid >> 2;        // 0: a rows, 1: b rows
    int q  = wid & 3;         // position quarter / w-tile
    int nt0 = q * 7, ntN = (q == 3) ? 4 : 7;
    float* outbase = g_part + ((long)n * 96 + pt) * 625;

    for (int i = 0; i < 3; i++) {
        float acc2[4] = {0.f, 0.f, 0.f, 0.f};
#pragma unroll
        for (int h = 0; h < 2; h++) {     // r-halves (16 rows each)
            __syncthreads();   // Xh staged / previous logits reads done
            // ---- a/b mma: one m16 row-tile x ntN n8 pos-tiles, K=64 ----
            float acc1[7][4] = {};
            int mb = ab ? (6 + 2 * i + h) : (2 * i + h);
#pragma unroll
            for (int ks = 0; ks < 4; ks++) {
                const uint4* fp = (const uint4*)g_Wabf + ((long)(mb * 4 + ks) * 32 + lane) * 2;
                uint4 Ah = fp[0];
                int bk = ks * 16 + lc2;
#pragma unroll
                for (int j = 0; j < 7; j++) {
                    if (j < ntN) {
                        int bp = (nt0 + j) * 8 + lr;
                        unsigned b0 = *(const unsigned*)&Xh[bp][bk];
                        unsigned b1 = *(const unsigned*)&Xh[bp][bk + 8];
                        mma16816(acc1[j], Ah, b0, b1);
                    }
                }
            }
            // ---- epilogue: +bias, transpose into At/Bt ----
            int growBase = (ab ? 96 : 0) + 32 * i + h * 16;
            float bs0 = g_bab_pad[growBase + lr];
            float bs1 = g_bab_pad[growBase + lr + 8];
            unsigned short (*Dt)[AP] = ab ? Bt : At;
#pragma unroll
            for (int j = 0; j < 7; j++) {
                if (j < ntN) {
                    int p0 = (nt0 + j) * 8 + lc2;
                    int v0 = p0 % 25, t0 = p0 / 25;
                    int p1 = p0 + 1;
                    int v1 = p1 % 25, t1 = p1 / 25;
                    Dt[v0][lr * 8 + t0]       = bf_hi(acc1[j][0] + bs0);
                    Dt[v1][lr * 8 + t1]       = bf_hi(acc1[j][1] + bs0);
                    Dt[v0][(lr + 8) * 8 + t0] = bf_hi(acc1[j][2] + bs1);
                    Dt[v1][(lr + 8) * 8 + t1] = bf_hi(acc1[j][3] + bs1);
                }
            }
            __syncthreads();
            // ---- logits mma: C[v][w] += sum_{k=128} At[v][k] Bt[w][k] ----
            int vr = ab * 16 + lr;     // warp's v rows
            int wr = q * 8 + lr;       // warp's w rows
#pragma unroll
            for (int ks = 0; ks < 8; ks++) {
                int kb = ks * 16 + lc2;
                uint4 Af;
                Af.x = *(const unsigned*)&At[vr][kb];
                Af.y = *(const unsigned*)&At[vr + 8][kb];
                Af.z = *(const unsigned*)&At[vr][kb + 8];
                Af.w = *(const unsigned*)&At[vr + 8][kb + 8];
                unsigned bb0 = *(const unsigned*)&Bt[wr][kb];
                unsigned bb1 = *(const unsigned*)&Bt[wr][kb + 8];
                mma16816(acc2, Af, bb0, bb1);
            }
        }
        // store partial logits, transposed [w*25+v]
        float* outp = outbase + (long)i * 32 * 625;
        int v = ab * 16 + lr, w = q * 8 + lc2;
        if (w < 25) {
            if (v < 25)     outp[w * 25 + v]     = acc2[0];
            if (v + 8 < 25) outp[w * 25 + v + 8] = acc2[2];
            if (w + 1 < 25) {
                if (v < 25)     outp[(w + 1) * 25 + v]     = acc2[1];
                if (v + 8 < 25) outp[(w + 1) * 25 + v + 8] = acc2[3];
            }
        }
    }
}

#define LDB 72   // smem row pitch for 128-wide GEMM staging

// =============== GEMM: down = Wdown @ x, 3-term, fp16 out, + stats =========
// grid (50, 1, 64)
__global__ __launch_bounds__(256, 2) void gemm_down_k(const float* __restrict__ x,
                                                      const float* __restrict__ bdown) {
    __shared__ __align__(16) unsigned short Bh[128][LDB];
    __shared__ __align__(16) unsigned short Bl[128][LDB];
    __shared__ float redS[8][8][4], redQ[8][8][4];
    int tid = threadIdx.x, wid = tid >> 5, lane = tid & 31;
    int n = blockIdx.z, pBase = blockIdx.x * 128;
    int warpM = (wid >> 1) * 32, warpP = (wid & 1) * 64;
    float acc[2][8][4] = {};

    const float* inp = x + (long)n * (64L * TV) + pBase;
    int sp = tid & 127, skh = (tid >> 7) * 32;
    const float* colp = inp + (long)skh * TV + sp;
#pragma unroll
    for (int j = 0; j < 32; j += 2) {
        float v0 = colp[(long)j * TV];
        float v1 = colp[(long)(j + 1) * TV];
        *(unsigned*)&Bh[sp][skh + j] = pack_hi(v0, v1);
        *(unsigned*)&Bl[sp][skh + j] = pack_lo(v0, v1);
    }
    __syncthreads();

#pragma unroll
    for (int ks = 0; ks < 4; ks++) {
        uint4 Ah[2], Al[2];
#pragma unroll
        for (int mi = 0; mi < 2; mi++) {
            int mb = (wid >> 1) * 2 + mi;
            const uint4* fp = (const uint4*)g_Wdnf + ((long)(mb * 4 + ks) * 32 + lane) * 2;
            Ah[mi] = fp[0];
            Al[mi] = fp[1];
        }
        int bk = ks * 16 + (lane & 3) * 2;
#pragma unroll
        for (int ni = 0; ni < 8; ni++) {
            int bp = warpP + ni * 8 + (lane >> 2);
            unsigned bh0 = *(const unsigned*)&Bh[bp][bk];
            unsigned bh1 = *(const unsigned*)&Bh[bp][bk + 8];
            unsigned bl0 = *(const unsigned*)&Bl[bp][bk];
            unsigned bl1 = *(const unsigned*)&Bl[bp][bk + 8];
#pragma unroll
            for (int mi = 0; mi < 2; mi++) {
                mma16816(acc[mi][ni], Ah[mi], bh0, bh1);
                mma16816(acc[mi][ni], Ah[mi], bl0, bl1);
                mma16816(acc[mi][ni], Al[mi], bh0, bh1);
            }
        }
    }

    float ssum[2][2] = {}, ssq[2][2] = {};
#pragma unroll
    for (int mi = 0; mi < 2; mi++) {
        int m = warpM + mi * 16 + (lane >> 2);
        float b0 = bdown[m], b1 = bdown[m + 8];
        __half* op = g_zdh + ((long)n * 128 + m) * TV + pBase + warpP + (lane & 3) * 2;
#pragma unroll
        for (int ni = 0; ni < 8; ni++) {
            float v0 = acc[mi][ni][0] + b0, v1 = acc[mi][ni][1] + b0;
            float v2 = acc[mi][ni][2] + b1, v3 = acc[mi][ni][3] + b1;
            __half2 h01 = make_half2(__float2half_rn(v0), __float2half_rn(v1));
            __half2 h23 = make_half2(__float2half_rn(v2), __float2half_rn(v3));
            *(__half2*)(op + ni * 8) = h01;
            *(__half2*)(op + ni * 8 + 8L * TV) = h23;
            ssum[mi][0] += v0 + v1; ssq[mi][0] += v0 * v0 + v1 * v1;
            ssum[mi][1] += v2 + v3; ssq[mi][1] += v2 * v2 + v3 * v3;
        }
    }
#pragma unroll
    for (int mi = 0; mi < 2; mi++)
#pragma unroll
        for (int hi = 0; hi < 2; hi++) {
            float s = ssum[mi][hi], q = ssq[mi][hi];
            s += __shfl_xor_sync(0xffffffffu, s, 1);
            s += __shfl_xor_sync(0xffffffffu, s, 2);
            q += __shfl_xor_sync(0xffffffffu, q, 1);
            q += __shfl_xor_sync(0xffffffffu, q, 2);
            if ((lane & 3) == 0) {
                redS[wid][lane >> 2][mi * 2 + hi] = s;
                redQ[wid][lane >> 2][mi * 2 + hi] = q;
            }
        }
    __syncthreads();
    if (tid < 128) {
        int r = tid, mt = r >> 5, rr = r & 31;
        int mi = rr >> 4, hi = (rr >> 3) & 1, q8 = rr & 7;
        int w0 = mt * 2;
        float S = redS[w0][q8][mi * 2 + hi] + redS[w0 + 1][q8][mi * 2 + hi];
        float Q = redQ[w0][q8][mi * 2 + hi] + redQ[w0 + 1][q8][mi * 2 + hi];
        long idx = (((long)64 + n) * 64 + blockIdx.x) * 128 + r;   // stride-64 layout
        g_psum[idx] = S;
        g_psq[idx] = Q;
    }
}

// ---------------- softmax: block per (n,i), smem partial reduce ------------
__global__ __launch_bounds__(256) void softmax2_k() {
    __shared__ float P[625];
    int bx = blockIdx.x;
    int n = bx / 3, i = bx % 3;
    int tid = threadIdx.x;
    const float* base = g_part + ((long)(n * 3 + i)) * 32 * 625;
    for (int f = tid; f < 625; f += 256) {
        float s = 0.f;
#pragma unroll
        for (int pt = 0; pt < 32; pt++) s += base[pt * 625 + f];
        P[f] = s * (1.f / 8192.f);
    }
    __syncthreads();
    if (tid < 25) {
        int w = tid;
        float lg[25];
        float mx = -1e30f;
#pragma unroll
        for (int v = 0; v < 25; v++) { lg[v] = P[w * 25 + v]; mx = fmaxf(mx, lg[v]); }
        float sum = 0.f;
#pragma unroll
        for (int v = 0; v < 25; v++) { lg[v] = expf(lg[v] - mx); sum += lg[v]; }
        float inv = 1.f / sum;
        float* sp = g_S + (long)(n * 3 + i) * 625 + w * 25;
        const float* at = g_Atot + i * 625;
#pragma unroll
        for (int v = 0; v < 25; v++) sp[v] = lg[v] * inv + at[v * 25 + w];
    }
}

// ====== fused xs + y GEMM: y[m,p] = sum_i Wd_i[m,:] (x S_i)[:,p] + bias ====
// grid (64 pt, 64 n); P-tile = 100 positions (4 whole t's). Block 256.
// Per subset i: xs sub-tile computed in smem via mma, consumed immediately.
__global__ __launch_bounds__(256, 2) void xsy_k(const float* __restrict__ x) {
    __shared__ unsigned short Xt[4][64][40];              // [t][c][v pad32]
    __shared__ unsigned short Ss[3][32][40];              // [i][w][v]
    __shared__ __align__(16) unsigned short XS[112][72];  // [p][c] (rows>=100 garbage)
    __shared__ float redS[8][8][8], redQ[8][8][8];
    int tid = threadIdx.x, wid = tid >> 5, lane = tid & 31;
    int lr = lane >> 2, lc2 = (lane & 3) * 2;
    int ptB = blockIdx.x, n = blockIdx.y;
    int pBase = ptB * 100;

    // zero padded operands
    for (int f = tid; f < 5120; f += 256) ((unsigned*)Xt)[f] = 0;
    for (int f = tid; f < 1920; f += 256) ((unsigned*)Ss)[f] = 0;
    __syncthreads();

    const float* spt = g_S + (long)n * 1875;   // S^T: [i][w][v]
    for (int f = tid; f < 1875; f += 256) {
        int i = f / 625, r = f - i * 625, w = r / 25, v = r - w * 25;
        Ss[i][w][v] = bf_hi(spt[f]);
    }
    const float* xb = x + (long)n * 409600;
    for (int f = tid; f < 6400; f += 256) {
        int t = f / 1600, r = f - t * 1600, c = r / 25, v = r - c * 25;
        Xt[t][c][v] = bf_hi(xb[(long)c * TV + pBase + t * 25 + v]);
    }
    __syncthreads();

    int warpM = (wid >> 2) * 64;   // y m-range: 4 m-tiles
    int warpW = (wid & 3) * 25;    // y p-window (25 positions)
    float acc[4][4][4] = {};       // [mt][nt][frag]

    for (int i = 0; i < 3; i++) {
        // ---- xs phase: R^T[c][w] = Xt[c][v] @ Ss_i^T[w][v]; warp: t, c-half
        int t = wid >> 1, ch0 = (wid & 1) * 32;
        float xacc[2][4][4] = {};
#pragma unroll
        for (int ks = 0; ks < 2; ks++) {
            uint4 Af[2];
#pragma unroll
            for (int mi = 0; mi < 2; mi++) {
                int row = ch0 + mi * 16 + lr;
                Af[mi].x = *(const unsigned*)&Xt[t][row][ks * 16 + lc2];
                Af[mi].y = *(const unsigned*)&Xt[t][row + 8][ks * 16 + lc2];
                Af[mi].z = *(const unsigned*)&Xt[t][row][ks * 16 + lc2 + 8];
                Af[mi].w = *(const unsigned*)&Xt[t][row + 8][ks * 16 + lc2 + 8];
            }
#pragma unroll
            for (int nt = 0; nt < 4; nt++) {
                unsigned b0 = *(const unsigned*)&Ss[i][nt * 8 + lr][ks * 16 + lc2];
                unsigned b1 = *(const unsigned*)&Ss[i][nt * 8 + lr][ks * 16 + lc2 + 8];
                mma16816(xacc[0][nt], Af[0], b0, b1);
                mma16816(xacc[1][nt], Af[1], b0, b1);
            }
        }
        __syncthreads();   // prior y-phase XS reads done
#pragma unroll
        for (int mi = 0; mi < 2; mi++) {
#pragma unroll
            for (int nt = 0; nt < 4; nt++) {
                int w = nt * 8 + lc2;
                int c = ch0 + mi * 16 + lr;
                if (w < 25) {
                    XS[t * 25 + w][c]     = bf_hi(xacc[mi][nt][0]);
                    XS[t * 25 + w][c + 8] = bf_hi(xacc[mi][nt][2]);
                    if (w + 1 < 25) {
                        XS[t * 25 + w + 1][c]     = bf_hi(xacc[mi][nt][1]);
                        XS[t * 25 + w + 1][c + 8] = bf_hi(xacc[mi][nt][3]);
                    }
                }
            }
        }
        __syncthreads();
        // ---- y phase: k-chunk i (64 k) against XS ----
#pragma unroll
        for (int ks = 0; ks < 4; ks++) {
            int kg = i * 4 + ks;
            uint4 Ah[4];
#pragma unroll
            for (int mt = 0; mt < 4; mt++) {
                int mb = (wid >> 2) * 4 + mt;
                const uint4* fp = (const uint4*)g_Wyf + ((long)(mb * 12 + kg) * 32 + lane) * 2;
                Ah[mt] = fp[0];
            }
            int bk = ks * 16 + lc2;
#pragma unroll
            for (int nt = 0; nt < 4; nt++) {
                int bp = warpW + nt * 8 + lr;
                unsigned b0 = *(const unsigned*)&XS[bp][bk];
                unsigned b1 = *(const unsigned*)&XS[bp][bk + 8];
#pragma unroll
                for (int mt = 0; mt < 4; mt++)
                    mma16816(acc[mt][nt], Ah[mt], b0, b1);
            }
        }
    }

    // ---- stats from accumulators (guard w<25) ----
    float ssum[4][2] = {}, ssq[4][2] = {};
#pragma unroll
    for (int mt = 0; mt < 4; mt++) {
        int m = warpM + mt * 16 + lr;
        float b0 = g_by[m], b1 = g_by[m + 8];
#pragma unroll
        for (int nt = 0; nt < 4; nt++) {
            int w = nt * 8 + lc2;
            if (w < 25) {
                float v0 = acc[mt][nt][0] + b0, v2 = acc[mt][nt][2] + b1;
                ssum[mt][0] += v0; ssq[mt][0] += v0 * v0;
                ssum[mt][1] += v2; ssq[mt][1] += v2 * v2;
            }
            if (w + 1 < 25) {
                float v1 = acc[mt][nt][1] + b0, v3 = acc[mt][nt][3] + b1;
                ssum[mt][0] += v1; ssq[mt][0] += v1 * v1;
                ssum[mt][1] += v3; ssq[mt][1] += v3 * v3;
            }
        }
    }
#pragma unroll
    for (int mt = 0; mt < 4; mt++)
#pragma unroll
        for (int hi = 0; hi < 2; hi++) {
            float s = ssum[mt][hi], q = ssq[mt][hi];
            s += __shfl_xor_sync(0xffffffffu, s, 1);
            s += __shfl_xor_sync(0xffffffffu, s, 2);
            q += __shfl_xor_sync(0xffffffffu, q, 1);
            q += __shfl_xor_sync(0xffffffffu, q, 2);
            if ((lane & 3) == 0) {
                redS[wid][lr][mt * 2 + hi] = s;
                redQ[wid][lr][mt * 2 + hi] = q;
            }
        }
    __syncthreads();
    if (tid < 128) {
        int r = tid;
        int h = r >> 6, rr = r & 63;
        int mt = rr >> 4, rem = rr & 15;
        int hi = rem >> 3, lrr = rem & 7;
        float S = 0.f, Q = 0.f;
#pragma unroll
        for (int j = 0; j < 4; j++) {
            S += redS[h * 4 + j][lrr][mt * 2 + hi];
            Q += redQ[h * 4 + j][lrr][mt * 2 + hi];
        }
        long idx = ((long)n * 64 + ptB) * 128 + r;
        g_psum[idx] = S;
        g_psq[idx] = Q;
    }

    // ---- staged epilogue: reuse Xt as St[64][104] bf16 ----
    __syncthreads();
    unsigned short (*St)[104] = (unsigned short(*)[104])Xt;
#pragma unroll
    for (int h = 0; h < 2; h++) {
        if ((wid >> 2) == h) {
#pragma unroll
            for (int mt = 0; mt < 4; mt++) {
                int m = warpM + mt * 16 + lr;
                float b0 = g_by[m], b1 = g_by[m + 8];
                int r0 = mt * 16 + lr;
#pragma unroll
                for (int nt = 0; nt < 4; nt++) {
                    int w = nt * 8 + lc2;
                    int col = warpW + w;
                    if (w < 25) {
                        St[r0][col]     = bf_hi(acc[mt][nt][0] + b0);
                        St[r0 + 8][col] = bf_hi(acc[mt][nt][2] + b1);
                        if (w + 1 < 25) {
                            St[r0][col + 1]     = bf_hi(acc[mt][nt][1] + b0);
                            St[r0 + 8][col + 1] = bf_hi(acc[mt][nt][3] + b1);
                        }
                    }
                }
            }
        }
        __syncthreads();
        for (int f = tid; f < 1600; f += 256) {
            int r = f / 25, c4 = f - r * 25;
            uint2 v = *(const uint2*)&St[r][c4 * 4];
            *(uint2*)(g_zy + ((long)n * 128 + h * 64 + r) * TV + pBase + c4 * 4) = v;
        }
        __syncthreads();
    }
}

// ---------------- stats reduce: per-channel mean/var from block partials ---
__global__ __launch_bounds__(256) void stats_reduce(
    const float* __restrict__ gbn, const float* __restrict__ bbn,
    const float* __restrict__ gdn, const float* __restrict__ bdn)
{
    int qch = blockIdx.x;
    int half = qch >> 7, r = qch & 127;
    int tid = threadIdx.x;
    int limit = half ? 50 : 64;          // blocks per n (down:50, y:64)
    int total = 64 * limit;
    float s = 0.f, q = 0.f;
    for (int f = tid; f < total; f += 256) {
        int nb = f / limit, blk = f - nb * limit;
        long idx = (((long)half * 64 + nb) * 64 + blk) * 128 + r;
        s += g_psum[idx];
        q += g_psq[idx];
    }
    __shared__ float rs[256], rq[256];
    rs[tid] = s; rq[tid] = q;
    __syncthreads();
    for (int st = 128; st > 0; st >>= 1) {
        if (tid < st) { rs[tid] += rs[tid + st]; rq[tid] += rq[tid + st]; }
        __syncthreads();
    }
    if (tid == 0) {
        const float inv_m = 1.f / 409600.f;
        float mean = rs[0] * inv_m;
        float var  = rq[0] * inv_m - mean * mean;
        float rinv = rsqrtf(var + 1e-5f);
        float gamma = half ? gdn[r] : gbn[r];
        float beta  = half ? bdn[r] : bbn[r];
        g_alpha[qch] = gamma * rinv;
        g_bet[qch]   = beta - mean * gamma * rinv;
    }
}

// ---------------- fused epilogue: out = BN_y(y) + BN_d(down) ---------------
__global__ __launch_bounds__(256) void final_kernel(float* __restrict__ out) {
    int idx = blockIdx.x * 256 + threadIdx.x;
    int p4 = idx % 1600;
    int o  = (idx / 1600) & 127;
    int n  = idx / 204800;
    long e = ((long)n * 128 + o) * TV + p4 * 4;
    uint2 yb = *(const uint2*)(g_zy + e);
    __nv_bfloat162 y01 = *(__nv_bfloat162*)&yb.x;
    __nv_bfloat162 y23 = *(__nv_bfloat162*)&yb.y;
    uint2 db = *(const uint2*)(g_zdh + e);
    __half2 d01 = *(__half2*)&db.x;
    __half2 d23 = *(__half2*)&db.y;
    float a1 = g_alpha[o],       c1 = g_bet[o];
    float a2 = g_alpha[o + 128], c2 = g_bet[o + 128];
    float4 r;
    r.x = fmaf(a1, __bfloat162float(y01.x), c1) + fmaf(a2, __half2float(d01.x), c2);
    r.y = fmaf(a1, __bfloat162float(y01.y), c1) + fmaf(a2, __half2float(d01.y), c2);
    r.z = fmaf(a1, __bfloat162float(y23.x), c1) + fmaf(a2, __half2float(d23.x), c2);
    r.w = fmaf(a1, __bfloat162float(y23.y), c1) + fmaf(a2, __half2float(d23.y), c2);
    ((float4*)out)[idx] = r;
}

// ---------------- launcher -------------------------------------------------
extern "C" void kernel_launch(void* const* d_in, const int* in_sizes, int n_in,
                              void* d_out, int out_size) {
    const float* x     = (const float*)d_in[0];
    const float* A     = (const float*)d_in[1];
    const float* PA    = (const float*)d_in[2];
    const float* Wa    = (const float*)d_in[3];
    const float* ba    = (const float*)d_in[4];
    const float* Wb    = (const float*)d_in[5];
    const float* bb    = (const float*)d_in[6];
    const float* Wd    = (const float*)d_in[7];
    const float* bd    = (const float*)d_in[8];
    const float* Wdown = (const float*)d_in[9];
    const float* bdown = (const float*)d_in[10];
    const float* gbn   = (const float*)d_in[11];
    const float* bbn   = (const float*)d_in[12];
    const float* gdn   = (const float*)d_in[13];
    const float* bdn   = (const float*)d_in[14];
    float* out = (float*)d_out;

    // static side stream + events (created on the pre-capture correctness call)
    static cudaStream_t s_down = nullptr;
    static cudaEvent_t ev_fork = nullptr, ev_join = nullptr;
    if (!s_down) {
        cudaStreamCreateWithFlags(&s_down, cudaStreamNonBlocking);
        cudaEventCreateWithFlags(&ev_fork, cudaEventDisableTiming);
        cudaEventCreateWithFlags(&ev_join, cudaEventDisableTiming);
    }

    prep_kernel<<<48, 256>>>(Wa, ba, Wb, bb, Wd, bd, Wdown, A, PA);

    // fork: down branch runs concurrently with the attention chain
    cudaEventRecord(ev_fork, 0);
    cudaStreamWaitEvent(s_down, ev_fork, 0);
    gemm_down_k<<<dim3(50, 1, 64), 256, 0, s_down>>>(x, bdown);
    cudaEventRecord(ev_join, s_down);

    ablogits_k<<<dim3(32, 64), 256>>>(x);            // a/b + logits partials
    softmax2_k<<<192, 256>>>();                      // S^T -> g_S
    xsy_k<<<dim3(64, 64), 256>>>(x);                 // fused xs+y -> g_zy + stats

    // join before stats (needs down's partials) and final (needs g_zdh)
    cudaStreamWaitEvent(0, ev_join, 0);
    stats_reduce<<<256, 256>>>(gbn, bbn, gdn, bdn);
    final_kernel<<<51200, 256>>>(out);
}

// round 16
// speedup vs baseline: 1.4929x; 1.4929x over previous
#include <cuda_runtime.h>
#include <cuda_bf16.h>
#include <cuda_fp16.h>
#include <cstdint>

#define TV 6400           // T*V = 256*25
#define NBATCH 64

// ---------------- scratch (device globals; no allocation allowed) ----------
__device__ __nv_bfloat16 g_xsb[78643200];  // (64,192,6400) bf16: xs (S-mixed x)
__device__ __nv_bfloat16 g_zy[52428800];   // (64,128,6400) bf16: y pre-BN
__device__ __half g_zdh[52428800];         // (64,128,6400) fp16: down pre-BN
__device__ float g_part[3840000];   // (64,3,32,625) logits partials, [w*25+v]
__device__ float g_S[120000];       // (64,3,25,25) S^T: [w][v]
__device__ float g_Atot[1875];      // A + PA  ([v][w])
__device__ float g_by[128];         // sum_i bd[i]
__device__ float g_bab_pad[256];    // [ba|bb|0pad]
__device__ float g_alpha[256];      // BN fused scale
__device__ float g_bet[256];        // BN fused shift
__device__ float g_psum[819200];    // (2,64,50,128) per-block channel sums
__device__ float g_psq[819200];     // (2,64,50,128) per-block channel sumsq
// weights pre-packed in m16n8k16 A-fragment order (hi uint4 then lo uint4 per lane)
__device__ __align__(16) unsigned g_Wabf[16384];  // 16 mb x 4 ks x 32 x 8
__device__ __align__(16) unsigned g_Wyf[24576];   // 8 mb x 12 ks x 32 x 8
__device__ __align__(16) unsigned g_Wdnf[8192];   // 8 mb x 4 ks x 32 x 8

// ---------------- bf16 hi/lo split helpers ---------------------------------
__device__ __forceinline__ unsigned short bf_hi(float v) {
    return __bfloat16_as_ushort(__float2bfloat16(v));
}
__device__ __forceinline__ unsigned short bf_lo(float v) {
    __nv_bfloat16 h = __float2bfloat16(v);
    return __bfloat16_as_ushort(__float2bfloat16(v - __bfloat162float(h)));
}
__device__ __forceinline__ unsigned pack_hi(float v0, float v1) {
    return (unsigned)bf_hi(v0) | ((unsigned)bf_hi(v1) << 16);
}
__device__ __forceinline__ unsigned pack_lo(float v0, float v1) {
    return (unsigned)bf_lo(v0) | ((unsigned)bf_lo(v1) << 16);
}

// ---------------- prep: biases, A+PA, fragment-packed weights --------------
__device__ __forceinline__ void frag_decode(int f, int nK16,
                                            int& row, int& col, bool& hi) {
    int r = f & 7, slot = f >> 3;
    int lane = slot & 31, t2 = slot >> 5;
    int ks = t2 % nK16, mb = t2 / nK16;
    int rr = r & 3;
    row = mb * 16 + (lane >> 2) + ((rr & 1) << 3);
    col = ks * 16 + (lane & 3) * 2 + ((rr & 2) << 2);
    hi = r < 4;
}

__global__ __launch_bounds__(256) void prep_kernel(
    const float* __restrict__ Wa, const float* __restrict__ ba,
    const float* __restrict__ Wb, const float* __restrict__ bb,
    const float* __restrict__ Wd, const float* __restrict__ bd,
    const float* __restrict__ Wdown,
    const float* __restrict__ A,  const float* __restrict__ PA)
{
    int stride = gridDim.x * blockDim.x;
    int g = blockIdx.x * blockDim.x + threadIdx.x;
    for (int f = g; f < 256; f += stride)
        g_bab_pad[f] = (f < 96) ? ba[f] : (f < 192 ? bb[f - 96] : 0.f);
    for (int f = g; f < 128; f += stride)
        g_by[f] = bd[f] + bd[128 + f] + bd[256 + f];
    for (int f = g; f < 1875; f += stride)
        g_Atot[f] = A[f] + PA[f];

    for (int f = g; f < 16384; f += stride) {
        int row, col; bool hi;
        frag_decode(f, 4, row, col, hi);
        float v0 = 0.f, v1 = 0.f;
        if (row < 96)       { v0 = Wa[row * 64 + col]; v1 = Wa[row * 64 + col + 1]; }
        else if (row < 192) { v0 = Wb[(row - 96) * 64 + col]; v1 = Wb[(row - 96) * 64 + col + 1]; }
        g_Wabf[f] = hi ? pack_hi(v0, v1) : pack_lo(v0, v1);
    }
    for (int f = g; f < 24576; f += stride) {
        int row, col; bool hi;
        frag_decode(f, 12, row, col, hi);
        int i = col >> 6, c = col & 63;
        float v0 = Wd[(i * 128 + row) * 64 + c];
        float v1 = Wd[(i * 128 + row) * 64 + c + 1];
        g_Wyf[f] = hi ? pack_hi(v0, v1) : pack_lo(v0, v1);
    }
    for (int f = g; f < 8192; f += stride) {
        int row, col; bool hi;
        frag_decode(f, 4, row, col, hi);
        float v0 = Wdown[row * 64 + col], v1 = Wdown[row * 64 + col + 1];
        g_Wdnf[f] = hi ? pack_hi(v0, v1) : pack_lo(v0, v1);
    }
}

// ---------------- mma.sync wrapper -----------------------------------------
__device__ __forceinline__ void mma16816(float* c, const uint4& a,
                                         unsigned b0, unsigned b1) {
    asm volatile(
        "mma.sync.aligned.m16n8k16.row.col.f32.bf16.bf16.f32 "
        "{%0,%1,%2,%3}, {%4,%5,%6,%7}, {%8,%9}, {%0,%1,%2,%3};"
        : "+f"(c[0]), "+f"(c[1]), "+f"(c[2]), "+f"(c[3])
        : "r"(a.x), "r"(a.y), "r"(a.z), "r"(a.w), "r"(b0), "r"(b1));
}

// ========== fused a/b conv + logits partials; no a/b gmem round-trip =======
// grid (32 pt, 64 n); P-tile = 200 positions (8 whole t's). Block 256.
#define XP 66    // Xh pitch (odd word stride -> conflict-free)
#define AP 136   // At/Bt pitch

__global__ __launch_bounds__(256, 2) void ablogits_k(const float* __restrict__ x) {
    __shared__ __align__(16) unsigned short Xh[200][XP];
    __shared__ __align__(16) unsigned short At[32][AP];  // a^T: [v][r*8+tl]
    __shared__ __align__(16) unsigned short Bt[32][AP];  // b^T: [w][r*8+tl]
    int tid = threadIdx.x, wid = tid >> 5, lane = tid & 31;
    int pt = blockIdx.x, n = blockIdx.y;
    int lr = lane >> 2, lc2 = (lane & 3) * 2;
    int pBase = pt * 200;

    // stage X tile: 64 ch x 200 pos, bf16-hi, pos-major
    const float* xb = x + (long)n * (64L * TV) + pBase;
    for (int f = tid; f < 12800; f += 256) {
        int c = f / 200, p = f - c * 200;
        Xh[p][c] = bf_hi(xb[(long)c * TV + p]);
    }

    int ab = wid >> 2;        // 0: a rows, 1: b rows
    int q  = wid & 3;         // position quarter / w-tile
    int nt0 = q * 7, ntN = (q == 3) ? 4 : 7;
    float* outbase = g_part + ((long)n * 96 + pt) * 625;

    for (int i = 0; i < 3; i++) {
        float acc2[4] = {0.f, 0.f, 0.f, 0.f};
#pragma unroll
        for (int h = 0; h < 2; h++) {     // r-halves (16 rows each)
            __syncthreads();   // Xh staged / previous logits reads done
            // ---- a/b mma: one m16 row-tile x ntN n8 pos-tiles, K=64 ----
            float acc1[7][4] = {};
            int mb = ab ? (6 + 2 * i + h) : (2 * i + h);
#pragma unroll
            for (int ks = 0; ks < 4; ks++) {
                const uint4* fp = (const uint4*)g_Wabf + ((long)(mb * 4 + ks) * 32 + lane) * 2;
                uint4 Ah = fp[0];
                int bk = ks * 16 + lc2;
#pragma unroll
                for (int j = 0; j < 7; j++) {
                    if (j < ntN) {
                        int bp = (nt0 + j) * 8 + lr;
                        unsigned b0 = *(const unsigned*)&Xh[bp][bk];
                        unsigned b1 = *(const unsigned*)&Xh[bp][bk + 8];
                        mma16816(acc1[j], Ah, b0, b1);
                    }
                }
            }
            // ---- epilogue: +bias, transpose into At/Bt ----
            int growBase = (ab ? 96 : 0) + 32 * i + h * 16;
            float bs0 = g_bab_pad[growBase + lr];
            float bs1 = g_bab_pad[growBase + lr + 8];
            unsigned short (*Dt)[AP] = ab ? Bt : At;
#pragma unroll
            for (int j = 0; j < 7; j++) {
                if (j < ntN) {
                    int p0 = (nt0 + j) * 8 + lc2;
                    int v0 = p0 % 25, t0 = p0 / 25;
                    int p1 = p0 + 1;
                    int v1 = p1 % 25, t1 = p1 / 25;
                    Dt[v0][lr * 8 + t0]       = bf_hi(acc1[j][0] + bs0);
                    Dt[v1][lr * 8 + t1]       = bf_hi(acc1[j][1] + bs0);
                    Dt[v0][(lr + 8) * 8 + t0] = bf_hi(acc1[j][2] + bs1);
                    Dt[v1][(lr + 8) * 8 + t1] = bf_hi(acc1[j][3] + bs1);
                }
            }
            __syncthreads();
            // ---- logits mma: C[v][w] += sum_{k=128} At[v][k] Bt[w][k] ----
            int vr = ab * 16 + lr;     // warp's v rows
            int wr = q * 8 + lr;       // warp's w rows
#pragma unroll
            for (int ks = 0; ks < 8; ks++) {
                int kb = ks * 16 + lc2;
                uint4 Af;
                Af.x = *(const unsigned*)&At[vr][kb];
                Af.y = *(const unsigned*)&At[vr + 8][kb];
                Af.z = *(const unsigned*)&At[vr][kb + 8];
                Af.w = *(const unsigned*)&At[vr + 8][kb + 8];
                unsigned bb0 = *(const unsigned*)&Bt[wr][kb];
                unsigned bb1 = *(const unsigned*)&Bt[wr][kb + 8];
                mma16816(acc2, Af, bb0, bb1);
            }
        }
        // store partial logits, transposed [w*25+v]
        float* outp = outbase + (long)i * 32 * 625;
        int v = ab * 16 + lr, w = q * 8 + lc2;
        if (w < 25) {
            if (v < 25)     outp[w * 25 + v]     = acc2[0];
            if (v + 8 < 25) outp[w * 25 + v + 8] = acc2[2];
            if (w + 1 < 25) {
                if (v < 25)     outp[(w + 1) * 25 + v]     = acc2[1];
                if (v + 8 < 25) outp[(w + 1) * 25 + v + 8] = acc2[3];
            }
        }
    }
}

#define LDB 72   // smem row pitch for 128-wide GEMM staging

// =============== GEMM: down = Wdown @ x, 3-term, fp16 out, + stats =========
// grid (50, 1, 64)
__global__ __launch_bounds__(256, 2) void gemm_down_k(const float* __restrict__ x,
                                                      const float* __restrict__ bdown) {
    __shared__ __align__(16) unsigned short Bh[128][LDB];
    __shared__ __align__(16) unsigned short Bl[128][LDB];
    __shared__ float redS[8][8][4], redQ[8][8][4];
    int tid = threadIdx.x, wid = tid >> 5, lane = tid & 31;
    int n = blockIdx.z, pBase = blockIdx.x * 128;
    int warpM = (wid >> 1) * 32, warpP = (wid & 1) * 64;
    float acc[2][8][4] = {};

    const float* inp = x + (long)n * (64L * TV) + pBase;
    int sp = tid & 127, skh = (tid >> 7) * 32;
    const float* colp = inp + (long)skh * TV + sp;
#pragma unroll
    for (int j = 0; j < 32; j += 2) {
        float v0 = colp[(long)j * TV];
        float v1 = colp[(long)(j + 1) * TV];
        *(unsigned*)&Bh[sp][skh + j] = pack_hi(v0, v1);
        *(unsigned*)&Bl[sp][skh + j] = pack_lo(v0, v1);
    }
    __syncthreads();

#pragma unroll
    for (int ks = 0; ks < 4; ks++) {
        uint4 Ah[2], Al[2];
#pragma unroll
        for (int mi = 0; mi < 2; mi++) {
            int mb = (wid >> 1) * 2 + mi;
            const uint4* fp = (const uint4*)g_Wdnf + ((long)(mb * 4 + ks) * 32 + lane) * 2;
            Ah[mi] = fp[0];
            Al[mi] = fp[1];
        }
        int bk = ks * 16 + (lane & 3) * 2;
#pragma unroll
        for (int ni = 0; ni < 8; ni++) {
            int bp = warpP + ni * 8 + (lane >> 2);
            unsigned bh0 = *(const unsigned*)&Bh[bp][bk];
            unsigned bh1 = *(const unsigned*)&Bh[bp][bk + 8];
            unsigned bl0 = *(const unsigned*)&Bl[bp][bk];
            unsigned bl1 = *(const unsigned*)&Bl[bp][bk + 8];
#pragma unroll
            for (int mi = 0; mi < 2; mi++) {
                mma16816(acc[mi][ni], Ah[mi], bh0, bh1);
                mma16816(acc[mi][ni], Ah[mi], bl0, bl1);
                mma16816(acc[mi][ni], Al[mi], bh0, bh1);
            }
        }
    }

    float ssum[2][2] = {}, ssq[2][2] = {};
#pragma unroll
    for (int mi = 0; mi < 2; mi++) {
        int m = warpM + mi * 16 + (lane >> 2);
        float b0 = bdown[m], b1 = bdown[m + 8];
        __half* op = g_zdh + ((long)n * 128 + m) * TV + pBase + warpP + (lane & 3) * 2;
#pragma unroll
        for (int ni = 0; ni < 8; ni++) {
            float v0 = acc[mi][ni][0] + b0, v1 = acc[mi][ni][1] + b0;
            float v2 = acc[mi][ni][2] + b1, v3 = acc[mi][ni][3] + b1;
            __half2 h01 = make_half2(__float2half_rn(v0), __float2half_rn(v1));
            __half2 h23 = make_half2(__float2half_rn(v2), __float2half_rn(v3));
            *(__half2*)(op + ni * 8) = h01;
            *(__half2*)(op + ni * 8 + 8L * TV) = h23;
            ssum[mi][0] += v0 + v1; ssq[mi][0] += v0 * v0 + v1 * v1;
            ssum[mi][1] += v2 + v3; ssq[mi][1] += v2 * v2 + v3 * v3;
        }
    }
#pragma unroll
    for (int mi = 0; mi < 2; mi++)
#pragma unroll
        for (int hi = 0; hi < 2; hi++) {
            float s = ssum[mi][hi], q = ssq[mi][hi];
            s += __shfl_xor_sync(0xffffffffu, s, 1);
            s += __shfl_xor_sync(0xffffffffu, s, 2);
            q += __shfl_xor_sync(0xffffffffu, q, 1);
            q += __shfl_xor_sync(0xffffffffu, q, 2);
            if ((lane & 3) == 0) {
                redS[wid][lane >> 2][mi * 2 + hi] = s;
                redQ[wid][lane >> 2][mi * 2 + hi] = q;
            }
        }
    __syncthreads();
    if (tid < 128) {
        int r = tid, mt = r >> 5, rr = r & 31;
        int mi = rr >> 4, hi = (rr >> 3) & 1, q8 = rr & 7;
        int w0 = mt * 2;
        float S = redS[w0][q8][mi * 2 + hi] + redS[w0 + 1][q8][mi * 2 + hi];
        float Q = redQ[w0][q8][mi * 2 + hi] + redQ[w0 + 1][q8][mi * 2 + hi];
        long idx = (((long)64 + n) * 50 + blockIdx.x) * 128 + r;
        g_psum[idx] = S;
        g_psq[idx] = Q;
    }
}

// ---------------- softmax: block per (n,i), smem partial reduce ------------
__global__ __launch_bounds__(256) void softmax2_k() {
    __shared__ float P[625];
    int bx = blockIdx.x;
    int n = bx / 3, i = bx % 3;
    int tid = threadIdx.x;
    const float* base = g_part + ((long)(n * 3 + i)) * 32 * 625;
    for (int f = tid; f < 625; f += 256) {
        float s = 0.f;
#pragma unroll
        for (int pt = 0; pt < 32; pt++) s += base[pt * 625 + f];
        P[f] = s * (1.f / 8192.f);
    }
    __syncthreads();
    if (tid < 25) {
        int w = tid;
        float lg[25];
        float mx = -1e30f;
#pragma unroll
        for (int v = 0; v < 25; v++) { lg[v] = P[w * 25 + v]; mx = fmaxf(mx, lg[v]); }
        float sum = 0.f;
#pragma unroll
        for (int v = 0; v < 25; v++) { lg[v] = expf(lg[v] - mx); sum += lg[v]; }
        float inv = 1.f / sum;
        float* sp = g_S + (long)(n * 3 + i) * 625 + w * 25;
        const float* at = g_Atot + i * 625;
#pragma unroll
        for (int v = 0; v < 25; v++) sp[v] = lg[v] * inv + at[v * 25 + w];
    }
}

// ============ xs via mma: OUT[m,w] = sum_v IN[m,v] S[v,w], per (n,i) =======
__global__ __launch_bounds__(256) void xs_mma_kernel(const float* __restrict__ x) {
    __shared__ unsigned short As[256][40];
    __shared__ unsigned short Ss[3][32][40];   // [i][w][v]
    __shared__ __align__(16) unsigned short Os[6400];
    int tid = threadIdx.x, wid = tid >> 5, lane = tid & 31;
    int n = blockIdx.y, mt = blockIdx.x;
    int lr = lane >> 2, kb = (lane & 3) * 2;

    for (int f = tid; f < 5120; f += 256) ((unsigned*)As)[f] = 0;
    for (int f = tid; f < 1920; f += 256) ((unsigned*)Ss)[f] = 0;
    __syncthreads();

    const float* spt = g_S + (long)n * 1875;   // S^T: [i][w][v]
    for (int f = tid; f < 1875; f += 256) {
        int i = f / 625, r = f - i * 625, w = r / 25, v = r - w * 25;
        Ss[i][w][v] = bf_hi(spt[f]);
    }
    const float* xb = x + (long)n * 409600 + (long)mt * 6400;
    for (int f = tid; f < 6400; f += 256) {
        int m = f / 25, v = f - m * 25;
        As[m][v] = bf_hi(xb[f]);
    }
    __syncthreads();

    for (int i = 0; i < 3; i++) {
        float acc[2][4][4] = {};
#pragma unroll
        for (int ksx = 0; ksx < 2; ksx++) {
            uint4 Af[2];
#pragma unroll
            for (int mi = 0; mi < 2; mi++) {
                int mrow = wid * 32 + mi * 16 + lr;
                Af[mi].x = *(const unsigned*)&As[mrow][ksx * 16 + kb];
                Af[mi].y = *(const unsigned*)&As[mrow + 8][ksx * 16 + kb];
                Af[mi].z = *(const unsigned*)&As[mrow][ksx * 16 + kb + 8];
                Af[mi].w = *(const unsigned*)&As[mrow + 8][ksx * 16 + kb + 8];
            }
#pragma unroll
            for (int nt = 0; nt < 4; nt++) {
                unsigned b0 = *(const unsigned*)&Ss[i][nt * 8 + lr][ksx * 16 + kb];
                unsigned b1 = *(const unsigned*)&Ss[i][nt * 8 + lr][ksx * 16 + kb + 8];
                mma16816(acc[0][nt], Af[0], b0, b1);
                mma16816(acc[1][nt], Af[1], b0, b1);
            }
        }
#pragma unroll
        for (int mi = 0; mi < 2; mi++) {
            int mrow = wid * 32 + mi * 16 + lr;
#pragma unroll
            for (int nt = 0; nt < 4; nt++) {
                int w = nt * 8 + kb;
                if (w < 25) {
                    Os[mrow * 25 + w] = bf_hi(acc[mi][nt][0]);
                    Os[(mrow + 8) * 25 + w] = bf_hi(acc[mi][nt][2]);
                    if (w + 1 < 25) {
                        Os[mrow * 25 + w + 1] = bf_hi(acc[mi][nt][1]);
                        Os[(mrow + 8) * 25 + w + 1] = bf_hi(acc[mi][nt][3]);
                    }
                }
            }
        }
        __syncthreads();
        const uint4* os4 = (const uint4*)Os;
        uint4* ob4 = (uint4*)(g_xsb + (long)(n * 192 + i * 64 + mt) * 6400);
        for (int f = tid; f < 800; f += 256) ob4[f] = os4[f];
        __syncthreads();
    }
}

// =============== GEMM: y = Wd_cat @ xs, bf16 in/out, + stats ===============
__global__ __launch_bounds__(256, 2) void gemm_y_k() {
    __shared__ __align__(16) unsigned short Bh[128][LDB];
    __shared__ float redS[8][8][4], redQ[8][8][4];
    int tid = threadIdx.x, wid = tid >> 5, lane = tid & 31;
    int n = blockIdx.z, pBase = blockIdx.x * 128;
    int warpM = (wid >> 1) * 32, warpP = (wid & 1) * 64;
    float acc[2][8][4] = {};

    const __nv_bfloat16* inb = g_xsb + (long)n * (192L * TV) + pBase;
    int pq = tid & 63, skq = (tid >> 6) * 16;

    for (int kc = 0; kc < 3; kc++) {
        __syncthreads();
        const __nv_bfloat16* colb = inb + (long)(kc * 64 + skq) * TV + pq * 2;
#pragma unroll
        for (int j = 0; j < 16; j++) {
            __nv_bfloat162 v = *(const __nv_bfloat162*)(colb + (long)j * TV);
            Bh[pq * 2][skq + j]     = __bfloat16_as_ushort(v.x);
            Bh[pq * 2 + 1][skq + j] = __bfloat16_as_ushort(v.y);
        }
        __syncthreads();
#pragma unroll
        for (int ks = 0; ks < 4; ks++) {
            int kg = kc * 4 + ks;
            uint4 Ah[2];
#pragma unroll
            for (int mi = 0; mi < 2; mi++) {
                int mb = (wid >> 1) * 2 + mi;
                const uint4* fp = (const uint4*)g_Wyf + ((long)(mb * 12 + kg) * 32 + lane) * 2;
                Ah[mi] = fp[0];
            }
            int bk = ks * 16 + (lane & 3) * 2;
#pragma unroll
            for (int ni = 0; ni < 8; ni++) {
                int bp = warpP + ni * 8 + (lane >> 2);
                unsigned bh0 = *(const unsigned*)&Bh[bp][bk];
                unsigned bh1 = *(const unsigned*)&Bh[bp][bk + 8];
#pragma unroll
                for (int mi = 0; mi < 2; mi++)
                    mma16816(acc[mi][ni], Ah[mi], bh0, bh1);
            }
        }
    }

    float ssum[2][2] = {}, ssq[2][2] = {};
#pragma unroll
    for (int mi = 0; mi < 2; mi++) {
        int m = warpM + mi * 16 + (lane >> 2);
        float b0 = g_by[m], b1 = g_by[m + 8];
#pragma unroll
        for (int ni = 0; ni < 8; ni++) {
            float v0 = acc[mi][ni][0] + b0, v1 = acc[mi][ni][1] + b0;
            float v2 = acc[mi][ni][2] + b1, v3 = acc[mi][ni][3] + b1;
            ssum[mi][0] += v0 + v1; ssq[mi][0] += v0 * v0 + v1 * v1;
            ssum[mi][1] += v2 + v3; ssq[mi][1] += v2 * v2 + v3 * v3;
        }
    }
#pragma unroll
    for (int mi = 0; mi < 2; mi++)
#pragma unroll
        for (int hi = 0; hi < 2; hi++) {
            float s = ssum[mi][hi], q = ssq[mi][hi];
            s += __shfl_xor_sync(0xffffffffu, s, 1);
            s += __shfl_xor_sync(0xffffffffu, s, 2);
            q += __shfl_xor_sync(0xffffffffu, q, 1);
            q += __shfl_xor_sync(0xffffffffu, q, 2);
            if ((lane & 3) == 0) {
                redS[wid][lane >> 2][mi * 2 + hi] = s;
                redQ[wid][lane >> 2][mi * 2 + hi] = q;
            }
        }
    __syncthreads();
    if (tid < 128) {
        int r = tid, mt = r >> 5, rr = r & 31;
        int mi = rr >> 4, hi = (rr >> 3) & 1, q8 = rr & 7;
        int w0 = mt * 2;
        float S = redS[w0][q8][mi * 2 + hi] + redS[w0 + 1][q8][mi * 2 + hi];
        float Q = redQ[w0][q8][mi * 2 + hi] + redQ[w0 + 1][q8][mi * 2 + hi];
        long idx = ((long)n * 50 + blockIdx.x) * 128 + r;
        g_psum[idx] = S;
        g_psq[idx] = Q;
    }

    __syncthreads();
    unsigned short (*St)[136] = (unsigned short(*)[136])Bh;
#pragma unroll
    for (int h = 0; h < 2; h++) {
        if ((wid >> 2) == h) {
#pragma unroll
            for (int mi = 0; mi < 2; mi++) {
                int m = warpM + mi * 16 + (lane >> 2);
                float b0 = g_by[m], b1 = g_by[m + 8];
                int r0 = warpM - h * 64 + mi * 16 + (lane >> 2);
#pragma unroll
                for (int ni = 0; ni < 8; ni++) {
                    int col = warpP + ni * 8 + (lane & 3) * 2;
                    __nv_bfloat162 p0, p1;
                    p0.x = __float2bfloat16(acc[mi][ni][0] + b0);
                    p0.y = __float2bfloat16(acc[mi][ni][1] + b0);
                    p1.x = __float2bfloat16(acc[mi][ni][2] + b1);
                    p1.y = __float2bfloat16(acc[mi][ni][3] + b1);
                    *(__nv_bfloat162*)&St[r0][col] = p0;
                    *(__nv_bfloat162*)&St[r0 + 8][col] = p1;
                }
            }
        }
        __syncthreads();
        int m0 = h * 64;
        for (int f = tid; f < 1024; f += 256) {
            int r = f >> 4, c = f & 15;
            uint4 v = *(const uint4*)&St[r][c * 8];
            *(uint4*)(g_zy + ((long)n * 128 + m0 + r) * TV + pBase + c * 8) = v;
        }
        __syncthreads();
    }
}

// ---------------- stats reduce: per-channel mean/var from block partials ---
__global__ __launch_bounds__(256) void stats_reduce(
    const float* __restrict__ gbn, const float* __restrict__ bbn,
    const float* __restrict__ gdn, const float* __restrict__ bdn)
{
    int qch = blockIdx.x;
    int half = qch >> 7, r = qch & 127;
    int tid = threadIdx.x;
    float s = 0.f, q = 0.f;
    for (int f = tid; f < 3200; f += 256) {
        long idx = (((long)half * 64 + f / 50) * 50 + (f % 50)) * 128 + r;
        s += g_psum[idx];
        q += g_psq[idx];
    }
    __shared__ float rs[256], rq[256];
    rs[tid] = s; rq[tid] = q;
    __syncthreads();
    for (int st = 128; st > 0; st >>= 1) {
        if (tid < st) { rs[tid] += rs[tid + st]; rq[tid] += rq[tid + st]; }
        __syncthreads();
    }
    if (tid == 0) {
        const float inv_m = 1.f / 409600.f;
        float mean = rs[0] * inv_m;
        float var  = rq[0] * inv_m - mean * mean;
        float rinv = rsqrtf(var + 1e-5f);
        float gamma = half ? gdn[r] : gbn[r];
        float beta  = half ? bdn[r] : bbn[r];
        g_alpha[qch] = gamma * rinv;
        g_bet[qch]   = beta - mean * gamma * rinv;
    }
}

// ---------------- fused epilogue: out = BN_y(y) + BN_d(down) ---------------
__global__ __launch_bounds__(256) void final_kernel(float* __restrict__ out) {
    int idx = blockIdx.x * 256 + threadIdx.x;
    int p4 = idx % 1600;
    int o  = (idx / 1600) & 127;
    int n  = idx / 204800;
    long e = ((long)n * 128 + o) * TV + p4 * 4;
    uint2 yb = *(const uint2*)(g_zy + e);
    __nv_bfloat162 y01 = *(__nv_bfloat162*)&yb.x;
    __nv_bfloat162 y23 = *(__nv_bfloat162*)&yb.y;
    uint2 db = *(const uint2*)(g_zdh + e);
    __half2 d01 = *(__half2*)&db.x;
    __half2 d23 = *(__half2*)&db.y;
    float a1 = g_alpha[o],       c1 = g_bet[o];
    float a2 = g_alpha[o + 128], c2 = g_bet[o + 128];
    float4 r;
    r.x = fmaf(a1, __bfloat162float(y01.x), c1) + fmaf(a2, __half2float(d01.x), c2);
    r.y = fmaf(a1, __bfloat162float(y01.y), c1) + fmaf(a2, __half2float(d01.y), c2);
    r.z = fmaf(a1, __bfloat162float(y23.x), c1) + fmaf(a2, __half2float(d23.x), c2);
    r.w = fmaf(a1, __bfloat162float(y23.y), c1) + fmaf(a2, __half2float(d23.y), c2);
    ((float4*)out)[idx] = r;
}

// ---------------- launcher -------------------------------------------------
extern "C" void kernel_launch(void* const* d_in, const int* in_sizes, int n_in,
                              void* d_out, int out_size) {
    const float* x     = (const float*)d_in[0];
    const float* A     = (const float*)d_in[1];
    const float* PA    = (const float*)d_in[2];
    const float* Wa    = (const float*)d_in[3];
    const float* ba    = (const float*)d_in[4];
    const float* Wb    = (const float*)d_in[5];
    const float* bb    = (const float*)d_in[6];
    const float* Wd    = (const float*)d_in[7];
    const float* bd    = (const float*)d_in[8];
    const float* Wdown = (const float*)d_in[9];
    const float* bdown = (const float*)d_in[10];
    const float* gbn   = (const float*)d_in[11];
    const float* bbn   = (const float*)d_in[12];
    const float* gdn   = (const float*)d_in[13];
    const float* bdn   = (const float*)d_in[14];
    float* out = (float*)d_out;

    // static side stream + events (created on the pre-capture correctness call)
    static cudaStream_t s_down = nullptr;
    static cudaEvent_t ev_fork = nullptr, ev_join = nullptr;
    if (!s_down) {
        cudaStreamCreateWithFlags(&s_down, cudaStreamNonBlocking);
        cudaEventCreateWithFlags(&ev_fork, cudaEventDisableTiming);
        cudaEventCreateWithFlags(&ev_join, cudaEventDisableTiming);
    }

    prep_kernel<<<48, 256>>>(Wa, ba, Wb, bb, Wd, bd, Wdown, A, PA);

    // fork: down branch runs concurrently with the attention chain
    cudaEventRecord(ev_fork, 0);
    cudaStreamWaitEvent(s_down, ev_fork, 0);
    gemm_down_k<<<dim3(50, 1, 64), 256, 0, s_down>>>(x, bdown);
    cudaEventRecord(ev_join, s_down);

    ablogits_k<<<dim3(32, 64), 256>>>(x);            // a/b + logits partials
    softmax2_k<<<192, 256>>>();                      // S^T -> g_S
    xs_mma_kernel<<<dim3(64, 64), 256>>>(x);         // xs -> g_xsb
    gemm_y_k<<<dim3(50, 1, 64), 256>>>();            // y -> g_zy + stats partials

    // join before stats (needs down's partials) and final (needs g_zdh)
    cudaStreamWaitEvent(0, ev_join, 0);
    stats_reduce<<<256, 256>>>(gbn, bbn, gdn, bdn);
    final_kernel<<<51200, 256>>>(out);
}